// round 13
// baseline (speedup 1.0000x reference)
#include <cuda_runtime.h>
#include <math.h>
#include <stdint.h>

#define BB  2
#define SSL 2048
#define DD  1024
#define HH  16
#define HDD 64
#define MSZ (BB*SSL)

// Scratch (allocation-free rule: device globals). All tf32 bit patterns:
// g_q  = tf32(0.125*log2e * Q), dim-interleaved within 8-groups
//        (dim j -> position 2*(j&3)+(j>>2))
// g_kt = tf32(softplus(K)), dim-interleaved (same scheme)
// g_vt = tf32(Q + K), TRANSPOSED per (b,h): [((b*HH+h)*HDD + d)*SSL + token]
__device__ uint32_t g_q [MSZ*DD];
__device__ uint32_t g_kt[MSZ*DD];
__device__ uint32_t g_vt[MSZ*DD];

// ---------------------------------------------------------------------------
// helpers
// ---------------------------------------------------------------------------
__device__ __forceinline__ uint32_t f2tf32(float x) {
    uint32_t r;
    asm("cvt.rna.tf32.f32 %0, %1;" : "=r"(r) : "f"(x));
    return r;
}

__device__ __forceinline__ float ex2f(float x) {
    float r;
    asm("ex2.approx.f32 %0, %1;" : "=f"(r) : "f"(x));
    return r;
}

__device__ __forceinline__ void mma_tf32(float c[4], const uint32_t a[4],
                                         uint32_t b0, uint32_t b1) {
    asm volatile(
        "mma.sync.aligned.m16n8k8.row.col.f32.tf32.tf32.f32 "
        "{%0,%1,%2,%3}, {%4,%5,%6,%7}, {%8,%9}, {%0,%1,%2,%3};"
        : "+f"(c[0]), "+f"(c[1]), "+f"(c[2]), "+f"(c[3])
        : "r"(a[0]), "r"(a[1]), "r"(a[2]), "r"(a[3]), "r"(b0), "r"(b1));
}

__device__ __forceinline__ float softplus_f(float x) {
    return (x > 15.0f) ? x : log1pf(__expf(x));
}

__device__ __forceinline__ void cpa16(void* s, const void* g) {
    uint32_t sa = (uint32_t)__cvta_generic_to_shared(s);
    asm volatile("cp.async.ca.shared.global [%0], [%1], 16;" :: "r"(sa), "l"(g));
}
#define CP_COMMIT() asm volatile("cp.async.commit_group;")
#define CP_WAIT0()  asm volatile("cp.async.wait_group 0;")

// Q scale: 1/sqrt(HD)=1/8 fused with log2(e) so softmax is a bare ex2.
#define QSCALE (0.125f * 1.44269504f)

// ---------------------------------------------------------------------------
// Fused projection (r6 body, known-good): Q and K on the same X tile.
// Epilogue writes tf32 bits: g_q (scaled, interleaved), g_kt (softplus,
// interleaved), g_vt (Q+K, transposed per (b,h): dim-major, token-contig).
// CTA 128m x 64n, k-tile 32, double-buffered smem.
// ---------------------------------------------------------------------------
#define XS_STR 36
#define WS_STR 72
#define XS_BUF (128*XS_STR)
#define WS_BUF (32*WS_STR)
#define PROJ_SMEM ((2*XS_BUF + 4*WS_BUF)*4)

__global__ void __launch_bounds__(256, 2) proj_tc(
    const float* __restrict__ X,
    const float* __restrict__ Wq, const float* __restrict__ bq,
    const float* __restrict__ Wk, const float* __restrict__ bk)
{
    extern __shared__ uint32_t psm[];
    uint32_t* XsB  = psm;
    uint32_t* WqsB = psm + 2*XS_BUF;
    uint32_t* WksB = WqsB + 2*WS_BUF;

    const int m0 = blockIdx.y * 128;
    const int n0 = blockIdx.x * 64;
    const int t    = threadIdx.x;
    const int warp = t >> 5;
    const int lane = t & 31;
    const int lq   = lane & 3;
    const int lr   = lane >> 2;
    const int wm = (warp >> 1) * 32;
    const int wn = (warp & 1) * 32;

    const int xr = t >> 1;
    const int xcb = (t & 1) * 4;
    const int wr = t >> 3;
    const int wcb = t & 7;

    float accq[2][4][4] = {};
    float acck[2][4][4] = {};

    {
        const float* xp = X + (size_t)(m0 + xr) * DD;
        #pragma unroll
        for (int j = 0; j < 4; j++) {
            int c = xcb + j;
            float4 f = *(const float4*)(xp + 4*c);
            *(uint4*)&XsB[xr*XS_STR + 4*c] =
                make_uint4(f2tf32(f.x), f2tf32(f.y), f2tf32(f.z), f2tf32(f.w));
        }
        const float* wqp = Wq + (size_t)wr * DD + n0;
        const float* wkp = Wk + (size_t)wr * DD + n0;
        #pragma unroll
        for (int j = 0; j < 2; j++) {
            int c = wcb + 8*j;
            float4 fq = *(const float4*)(wqp + 4*c);
            *(uint4*)&WqsB[wr*WS_STR + 4*c] =
                make_uint4(f2tf32(fq.x), f2tf32(fq.y), f2tf32(fq.z), f2tf32(fq.w));
            float4 fk = *(const float4*)(wkp + 4*c);
            *(uint4*)&WksB[wr*WS_STR + 4*c] =
                make_uint4(f2tf32(fk.x), f2tf32(fk.y), f2tf32(fk.z), f2tf32(fk.w));
        }
    }
    __syncthreads();

    for (int k0 = 0; k0 < DD; k0 += 32) {
        const int buf = (k0 >> 5) & 1;
        uint32_t* Xs  = XsB  + buf*XS_BUF;
        uint32_t* Wqs = WqsB + buf*WS_BUF;
        uint32_t* Wks = WksB + buf*WS_BUF;
        const bool more = (k0 + 32) < DD;

        float4 xst[4], wqst[2], wkst[2];
        if (more) {
            const float* xp = X + (size_t)(m0 + xr) * DD + k0 + 32;
            #pragma unroll
            for (int j = 0; j < 4; j++)
                xst[j] = *(const float4*)(xp + 4*(xcb + j));
            const float* wqp = Wq + (size_t)(k0 + 32 + wr) * DD + n0;
            const float* wkp = Wk + (size_t)(k0 + 32 + wr) * DD + n0;
            #pragma unroll
            for (int j = 0; j < 2; j++) {
                wqst[j] = *(const float4*)(wqp + 4*(wcb + 8*j));
                wkst[j] = *(const float4*)(wkp + 4*(wcb + 8*j));
            }
        }

        #pragma unroll
        for (int ks = 0; ks < 4; ks++) {
            int kb = ks * 8;
            uint32_t a[2][4];
            #pragma unroll
            for (int mt = 0; mt < 2; mt++) {
                int ar = wm + 16*mt + lr;
                a[mt][0] = Xs[ar*XS_STR + kb + lq];
                a[mt][1] = Xs[(ar+8)*XS_STR + kb + lq];
                a[mt][2] = Xs[ar*XS_STR + kb + lq + 4];
                a[mt][3] = Xs[(ar+8)*XS_STR + kb + lq + 4];
            }
            #pragma unroll
            for (int nt = 0; nt < 4; nt++) {
                int bc = wn + 8*nt + lr;
                uint32_t q0 = Wqs[(kb + lq)*WS_STR + bc];
                uint32_t q1 = Wqs[(kb + 4 + lq)*WS_STR + bc];
                uint32_t k0r = Wks[(kb + lq)*WS_STR + bc];
                uint32_t k1r = Wks[(kb + 4 + lq)*WS_STR + bc];
                #pragma unroll
                for (int mt = 0; mt < 2; mt++) {
                    mma_tf32(accq[mt][nt], a[mt], q0, q1);
                    mma_tf32(acck[mt][nt], a[mt], k0r, k1r);
                }
            }
        }

        if (more) {
            uint32_t* Xn  = XsB  + (buf^1)*XS_BUF;
            uint32_t* Wqn = WqsB + (buf^1)*WS_BUF;
            uint32_t* Wkn = WksB + (buf^1)*WS_BUF;
            #pragma unroll
            for (int j = 0; j < 4; j++) {
                float4 f = xst[j];
                *(uint4*)&Xn[xr*XS_STR + 4*(xcb + j)] =
                    make_uint4(f2tf32(f.x), f2tf32(f.y), f2tf32(f.z), f2tf32(f.w));
            }
            #pragma unroll
            for (int j = 0; j < 2; j++) {
                float4 fq = wqst[j];
                *(uint4*)&Wqn[wr*WS_STR + 4*(wcb + 8*j)] =
                    make_uint4(f2tf32(fq.x), f2tf32(fq.y), f2tf32(fq.z), f2tf32(fq.w));
                float4 fk = wkst[j];
                *(uint4*)&Wkn[wr*WS_STR + 4*(wcb + 8*j)] =
                    make_uint4(f2tf32(fk.x), f2tf32(fk.y), f2tf32(fk.z), f2tf32(fk.w));
            }
        }
        __syncthreads();
    }

    // epilogue: g_q/g_kt interleaved tf32 bits; g_vt transposed tf32 bits
    #pragma unroll
    for (int nt = 0; nt < 4; nt++) {
        int c = n0 + wn + 8*nt + 2*lq;
        float bqx = bq[c], bqy = bq[c+1];
        float bkx = bk[c], bky = bk[c+1];
        int cb = c & ~7, j = c & 7;
        int j0 = 2*(j&3) + (j>>2);
        int j1 = 2*((j+1)&3) + ((j+1)>>2);
        #pragma unroll
        for (int mt = 0; mt < 2; mt++) {
            #pragma unroll
            for (int half = 0; half < 2; half++) {
                int r = m0 + wm + 16*mt + lr + 8*half;
                float qx = accq[mt][nt][2*half+0] + bqx;
                float qy = accq[mt][nt][2*half+1] + bqy;
                float kx = acck[mt][nt][2*half+0] + bkx;
                float ky = acck[mt][nt][2*half+1] + bky;
                size_t off = (size_t)r * DD;
                g_q [off + cb + j0] = f2tf32(QSCALE*qx);
                g_q [off + cb + j1] = f2tf32(QSCALE*qy);
                g_kt[off + cb + j0] = f2tf32(softplus_f(kx));
                g_kt[off + cb + j1] = f2tf32(softplus_f(ky));
                // transposed V: index = (bb*1024 + h*64 + d)*SSL + token
                int token = r & (SSL-1);
                int bidx  = r >> 11;                 // r / SSL
                size_t vb = ((size_t)(bidx*1024 + c))*SSL + token;   // c = h*64+d
                g_vt[vb]       = f2tf32(qx+kx);
                g_vt[vb + SSL] = f2tf32(qy+ky);      // c+1 -> +SSL
            }
        }
    }
}

// ---------------------------------------------------------------------------
// Flash attention v8 (r12 base + dim-major V => LDS.64 PV loads):
// Q-tile 128, 256 threads (8 warps, warp tile 16x64), 2 CTAs/SM.
// Q/K dim-interleaved -> S-phase LDS.64. V stored dim-major per (b,h)
// in global; smem tile Vt[64 dims][64 keys] loaded with verbatim cp.async
// row copies -> PV B-fragments are LDS.64 at (8d+lr)*72 + 8nt+2lq
// (slot lq <-> key 8nt+2lq, slot lq+4 <-> key 8nt+2lq+1, matching the
// P-register mapping; conflict-free). No-max ex2 softmax; masked rows p=1.
// ---------------------------------------------------------------------------
#define AQ_STR 72
#define AK_STR 72
#define AV_STR 72
#define KBUF (64*AK_STR)
#define VBUF (64*AV_STR)
#define SMEM_ATTN ((128*AQ_STR + 2*KBUF + 2*VBUF)*4)

__global__ void __launch_bounds__(256, 2) attn_tc(
    const int* __restrict__ amask, float* __restrict__ out)
{
    extern __shared__ uint32_t smu[];
    uint32_t* Qs  = smu;                  // [128][AQ_STR] interleaved dims
    uint32_t* KsB = Qs + 128*AQ_STR;      // [2][64][AK_STR] interleaved dims
    uint32_t* VsB = KsB + 2*KBUF;         // [2][64 dims][AV_STR keys]

    const int qt = blockIdx.x, h = blockIdx.y, b = blockIdx.z;
    const int t    = threadIdx.x;
    const int warp = t >> 5;
    const int lane = t & 31;
    const int lq   = lane & 3;
    const int lr   = lane >> 2;
    const int r0 = warp*16 + lr, r1 = r0 + 8;
    const int qrow = t >> 1, qv = t & 1;   // Q loader: 128 rows x 2 threads
    const int krow = t >> 2, kv = t & 3;   // K/V loader: 64 rows x 4 threads

    const size_t vtb = ((size_t)(b*1024 + h*HDD + krow))*SSL;  // V dim-row base

    {   // Q tile + K/V tile 0, all async (verbatim row copies)
        const uint32_t* qg = g_q + ((size_t)(b*SSL + qt*128 + qrow))*DD + h*HDD;
        #pragma unroll
        for (int j = 0; j < 8; j++) {
            int c = 8*qv + j;
            cpa16(&Qs[qrow*AQ_STR + 4*c], qg + 4*c);
        }
        size_t base = ((size_t)(b*SSL + krow))*DD + h*HDD;
        #pragma unroll
        for (int j = 0; j < 4; j++) {
            int c = kv + 4*j;
            cpa16(&KsB[krow*AK_STR + 4*c], g_kt + base + 4*c);
            cpa16(&VsB[krow*AV_STR + 4*c], g_vt + vtb + 4*c);
        }
        CP_COMMIT();
    }
    const bool mA = (amask[b*SSL + qt*128 + r0] == 0);
    const bool mB = (amask[b*SSL + qt*128 + r1] == 0);

    float tl0 = 0.0f, tl1 = 0.0f;
    float accO[8][4] = {};

    for (int it = 0; it < SSL/64; it++) {
        CP_WAIT0();
        __syncthreads();            // current buf fully resident + visible
        const int buf = it & 1;
        uint32_t* Ks = KsB + buf*KBUF;
        uint32_t* Vs = VsB + buf*VBUF;

        if (it + 1 < SSL/64) {      // prefetch next tile into buf^1
            uint32_t* Kn = KsB + (buf^1)*KBUF;
            uint32_t* Vn = VsB + (buf^1)*VBUF;
            size_t base = ((size_t)(b*SSL + (it+1)*64 + krow))*DD + h*HDD;
            size_t vtn  = vtb + (it+1)*64;
            #pragma unroll
            for (int j = 0; j < 4; j++) {
                int c = kv + 4*j;
                cpa16(&Kn[krow*AK_STR + 4*c], g_kt + base + 4*c);
                cpa16(&Vn[krow*AV_STR + 4*c], g_vt + vtn + 4*c);
            }
            CP_COMMIT();
        }

        // ---- S' = (Q*qscale) @ K^T : warp computes 16x64, LDS.64 frags ----
        float accS[8][4] = {};
        #pragma unroll
        for (int ks = 0; ks < 8; ks++) {
            int kb = ks * 8;
            uint32_t a[4];
            uint2 u0 = *(const uint2*)&Qs[r0*AQ_STR + kb + 2*lq];
            uint2 u1 = *(const uint2*)&Qs[r1*AQ_STR + kb + 2*lq];
            a[0] = u0.x; a[1] = u1.x; a[2] = u0.y; a[3] = u1.y;
            #pragma unroll
            for (int nt = 0; nt < 8; nt++) {
                uint2 bb = *(const uint2*)&Ks[(8*nt + lr)*AK_STR + kb + 2*lq];
                mma_tf32(accS[nt], a, bb.x, bb.y);
            }
        }

        // ---- no-max softmax in registers: p = 2^(s'); masked rows p=1 ----
        #pragma unroll
        for (int nt = 0; nt < 8; nt++) {
            float p0 = mA ? 1.0f : ex2f(accS[nt][0]);
            float p1 = mA ? 1.0f : ex2f(accS[nt][1]);
            float p2 = mB ? 1.0f : ex2f(accS[nt][2]);
            float p3 = mB ? 1.0f : ex2f(accS[nt][3]);
            tl0 += p0 + p1;
            tl1 += p2 + p3;
            accS[nt][0] = p0; accS[nt][1] = p1;
            accS[nt][2] = p2; accS[nt][3] = p3;
        }

        // ---- O += P @ V : P regs feed A; V dim-major -> LDS.64 B frags ----
        #pragma unroll
        for (int nt = 0; nt < 8; nt++) {          // nt = key 8-block
            uint32_t a[4];
            a[0] = __float_as_uint(accS[nt][0]);  // P[r0][key 2lq]   -> slot lq
            a[1] = __float_as_uint(accS[nt][2]);  // P[r1][key 2lq]
            a[2] = __float_as_uint(accS[nt][1]);  // P[r0][key 2lq+1] -> slot lq+4
            a[3] = __float_as_uint(accS[nt][3]);  // P[r1][key 2lq+1]
            #pragma unroll
            for (int d = 0; d < 8; d++) {
                uint2 bb = *(const uint2*)&Vs[(8*d + lr)*AV_STR + 8*nt + 2*lq];
                mma_tf32(accO[d], a, bb.x, bb.y);
            }
        }
    }

    // ---- epilogue: reduce l across quad, write O / l ----
    tl0 += __shfl_xor_sync(0xffffffffu, tl0, 1);
    tl0 += __shfl_xor_sync(0xffffffffu, tl0, 2);
    tl1 += __shfl_xor_sync(0xffffffffu, tl1, 1);
    tl1 += __shfl_xor_sync(0xffffffffu, tl1, 2);
    float li0 = 1.0f / tl0, li1 = 1.0f / tl1;
    size_t row0 = (size_t)(b*SSL + qt*128 + r0) * DD + h*HDD;
    size_t row1 = (size_t)(b*SSL + qt*128 + r1) * DD + h*HDD;
    #pragma unroll
    for (int d = 0; d < 8; d++) {
        int col = 8*d + 2*lq;
        *(float2*)(out + row0 + col) = make_float2(accO[d][0]*li0, accO[d][1]*li0);
        *(float2*)(out + row1 + col) = make_float2(accO[d][2]*li1, accO[d][3]*li1);
    }
}

// ---------------------------------------------------------------------------
extern "C" void kernel_launch(void* const* d_in, const int* in_sizes, int n_in,
                              void* d_out, int out_size)
{
    const float* X     = (const float*)d_in[0];
    const int*   amask = (const int*)  d_in[1];
    const float* Wq    = (const float*)d_in[2];
    const float* bq    = (const float*)d_in[3];
    const float* Wk    = (const float*)d_in[4];
    const float* bk    = (const float*)d_in[5];
    float*       out   = (float*)d_out;

    cudaFuncSetAttribute(proj_tc,
                         cudaFuncAttributeMaxDynamicSharedMemorySize, PROJ_SMEM);
    cudaFuncSetAttribute(attn_tc,
                         cudaFuncAttributeMaxDynamicSharedMemorySize, SMEM_ATTN);

    proj_tc<<<dim3(DD/64, MSZ/128), 256, PROJ_SMEM>>>(X, Wq, bq, Wk, bk);
    attn_tc<<<dim3(SSL/128, HH, BB), 256, SMEM_ATTN>>>(amask, out);
}

// round 15
// speedup vs baseline: 1.0247x; 1.0247x over previous
#include <cuda_runtime.h>
#include <math.h>
#include <stdint.h>

#define BB  2
#define SSL 2048
#define DD  1024
#define HH  16
#define HDD 64
#define MSZ (BB*SSL)

// Scratch (allocation-free rule: device globals). All tf32 bit patterns:
// g_q  = tf32(0.125*log2e * Q), dim-interleaved within 8-groups
//        (dim j -> position 2*(j&3)+(j>>2))
// g_kt = tf32(softplus(K)), dim-interleaved (same scheme)
// g_vt = tf32(Q + K), TRANSPOSED per (b,h): [(b*1024 + col)*SSL + token]
__device__ uint32_t g_q [MSZ*DD];
__device__ uint32_t g_kt[MSZ*DD];
__device__ uint32_t g_vt[MSZ*DD];

// ---------------------------------------------------------------------------
// helpers
// ---------------------------------------------------------------------------
__device__ __forceinline__ uint32_t f2tf32(float x) {
    uint32_t r;
    asm("cvt.rna.tf32.f32 %0, %1;" : "=r"(r) : "f"(x));
    return r;
}

__device__ __forceinline__ float ex2f(float x) {
    float r;
    asm("ex2.approx.f32 %0, %1;" : "=f"(r) : "f"(x));
    return r;
}

__device__ __forceinline__ void mma_tf32(float c[4], const uint32_t a[4],
                                         uint32_t b0, uint32_t b1) {
    asm volatile(
        "mma.sync.aligned.m16n8k8.row.col.f32.tf32.tf32.f32 "
        "{%0,%1,%2,%3}, {%4,%5,%6,%7}, {%8,%9}, {%0,%1,%2,%3};"
        : "+f"(c[0]), "+f"(c[1]), "+f"(c[2]), "+f"(c[3])
        : "r"(a[0]), "r"(a[1]), "r"(a[2]), "r"(a[3]), "r"(b0), "r"(b1));
}

__device__ __forceinline__ float softplus_f(float x) {
    return (x > 15.0f) ? x : log1pf(__expf(x));
}

__device__ __forceinline__ void cpa16(void* s, const void* g) {
    uint32_t sa = (uint32_t)__cvta_generic_to_shared(s);
    asm volatile("cp.async.ca.shared.global [%0], [%1], 16;" :: "r"(sa), "l"(g));
}
#define CP_COMMIT() asm volatile("cp.async.commit_group;")
#define CP_WAIT0()  asm volatile("cp.async.wait_group 0;")

// Q scale: 1/sqrt(HD)=1/8 fused with log2(e) so softmax is a bare ex2.
#define QSCALE (0.125f * 1.44269504f)

// ---------------------------------------------------------------------------
// Fused projection (r6 body, known-good): Q and K on the same X tile.
// Epilogue writes tf32 bits: g_q (scaled, interleaved), g_kt (softplus,
// interleaved), g_vt (Q+K, transposed per (b,h): dim-major, token-contig).
// CTA 128m x 64n, k-tile 32, double-buffered smem.
// ---------------------------------------------------------------------------
#define XS_STR 36
#define WS_STR 72
#define XS_BUF (128*XS_STR)
#define WS_BUF (32*WS_STR)
#define PROJ_SMEM ((2*XS_BUF + 4*WS_BUF)*4)

__global__ void __launch_bounds__(256, 2) proj_tc(
    const float* __restrict__ X,
    const float* __restrict__ Wq, const float* __restrict__ bq,
    const float* __restrict__ Wk, const float* __restrict__ bk)
{
    extern __shared__ uint32_t psm[];
    uint32_t* XsB  = psm;
    uint32_t* WqsB = psm + 2*XS_BUF;
    uint32_t* WksB = WqsB + 2*WS_BUF;

    const int m0 = blockIdx.y * 128;
    const int n0 = blockIdx.x * 64;
    const int t    = threadIdx.x;
    const int warp = t >> 5;
    const int lane = t & 31;
    const int lq   = lane & 3;
    const int lr   = lane >> 2;
    const int wm = (warp >> 1) * 32;
    const int wn = (warp & 1) * 32;

    const int xr = t >> 1;
    const int xcb = (t & 1) * 4;
    const int wr = t >> 3;
    const int wcb = t & 7;

    float accq[2][4][4] = {};
    float acck[2][4][4] = {};

    {
        const float* xp = X + (size_t)(m0 + xr) * DD;
        #pragma unroll
        for (int j = 0; j < 4; j++) {
            int c = xcb + j;
            float4 f = *(const float4*)(xp + 4*c);
            *(uint4*)&XsB[xr*XS_STR + 4*c] =
                make_uint4(f2tf32(f.x), f2tf32(f.y), f2tf32(f.z), f2tf32(f.w));
        }
        const float* wqp = Wq + (size_t)wr * DD + n0;
        const float* wkp = Wk + (size_t)wr * DD + n0;
        #pragma unroll
        for (int j = 0; j < 2; j++) {
            int c = wcb + 8*j;
            float4 fq = *(const float4*)(wqp + 4*c);
            *(uint4*)&WqsB[wr*WS_STR + 4*c] =
                make_uint4(f2tf32(fq.x), f2tf32(fq.y), f2tf32(fq.z), f2tf32(fq.w));
            float4 fk = *(const float4*)(wkp + 4*c);
            *(uint4*)&WksB[wr*WS_STR + 4*c] =
                make_uint4(f2tf32(fk.x), f2tf32(fk.y), f2tf32(fk.z), f2tf32(fk.w));
        }
    }
    __syncthreads();

    for (int k0 = 0; k0 < DD; k0 += 32) {
        const int buf = (k0 >> 5) & 1;
        uint32_t* Xs  = XsB  + buf*XS_BUF;
        uint32_t* Wqs = WqsB + buf*WS_BUF;
        uint32_t* Wks = WksB + buf*WS_BUF;
        const bool more = (k0 + 32) < DD;

        float4 xst[4], wqst[2], wkst[2];
        if (more) {
            const float* xp = X + (size_t)(m0 + xr) * DD + k0 + 32;
            #pragma unroll
            for (int j = 0; j < 4; j++)
                xst[j] = *(const float4*)(xp + 4*(xcb + j));
            const float* wqp = Wq + (size_t)(k0 + 32 + wr) * DD + n0;
            const float* wkp = Wk + (size_t)(k0 + 32 + wr) * DD + n0;
            #pragma unroll
            for (int j = 0; j < 2; j++) {
                wqst[j] = *(const float4*)(wqp + 4*(wcb + 8*j));
                wkst[j] = *(const float4*)(wkp + 4*(wcb + 8*j));
            }
        }

        #pragma unroll
        for (int ks = 0; ks < 4; ks++) {
            int kb = ks * 8;
            uint32_t a[2][4];
            #pragma unroll
            for (int mt = 0; mt < 2; mt++) {
                int ar = wm + 16*mt + lr;
                a[mt][0] = Xs[ar*XS_STR + kb + lq];
                a[mt][1] = Xs[(ar+8)*XS_STR + kb + lq];
                a[mt][2] = Xs[ar*XS_STR + kb + lq + 4];
                a[mt][3] = Xs[(ar+8)*XS_STR + kb + lq + 4];
            }
            #pragma unroll
            for (int nt = 0; nt < 4; nt++) {
                int bc = wn + 8*nt + lr;
                uint32_t q0 = Wqs[(kb + lq)*WS_STR + bc];
                uint32_t q1 = Wqs[(kb + 4 + lq)*WS_STR + bc];
                uint32_t k0r = Wks[(kb + lq)*WS_STR + bc];
                uint32_t k1r = Wks[(kb + 4 + lq)*WS_STR + bc];
                #pragma unroll
                for (int mt = 0; mt < 2; mt++) {
                    mma_tf32(accq[mt][nt], a[mt], q0, q1);
                    mma_tf32(acck[mt][nt], a[mt], k0r, k1r);
                }
            }
        }

        if (more) {
            uint32_t* Xn  = XsB  + (buf^1)*XS_BUF;
            uint32_t* Wqn = WqsB + (buf^1)*WS_BUF;
            uint32_t* Wkn = WksB + (buf^1)*WS_BUF;
            #pragma unroll
            for (int j = 0; j < 4; j++) {
                float4 f = xst[j];
                *(uint4*)&Xn[xr*XS_STR + 4*(xcb + j)] =
                    make_uint4(f2tf32(f.x), f2tf32(f.y), f2tf32(f.z), f2tf32(f.w));
            }
            #pragma unroll
            for (int j = 0; j < 2; j++) {
                float4 fq = wqst[j];
                *(uint4*)&Wqn[wr*WS_STR + 4*(wcb + 8*j)] =
                    make_uint4(f2tf32(fq.x), f2tf32(fq.y), f2tf32(fq.z), f2tf32(fq.w));
                float4 fk = wkst[j];
                *(uint4*)&Wkn[wr*WS_STR + 4*(wcb + 8*j)] =
                    make_uint4(f2tf32(fk.x), f2tf32(fk.y), f2tf32(fk.z), f2tf32(fk.w));
            }
        }
        __syncthreads();
    }

    // epilogue: g_q/g_kt interleaved tf32 bits; g_vt transposed tf32 bits
    #pragma unroll
    for (int nt = 0; nt < 4; nt++) {
        int c = n0 + wn + 8*nt + 2*lq;
        float bqx = bq[c], bqy = bq[c+1];
        float bkx = bk[c], bky = bk[c+1];
        int cb = c & ~7, j = c & 7;
        int j0 = 2*(j&3) + (j>>2);
        int j1 = 2*((j+1)&3) + ((j+1)>>2);
        #pragma unroll
        for (int mt = 0; mt < 2; mt++) {
            #pragma unroll
            for (int half = 0; half < 2; half++) {
                int r = m0 + wm + 16*mt + lr + 8*half;
                float qx = accq[mt][nt][2*half+0] + bqx;
                float qy = accq[mt][nt][2*half+1] + bqy;
                float kx = acck[mt][nt][2*half+0] + bkx;
                float ky = acck[mt][nt][2*half+1] + bky;
                size_t off = (size_t)r * DD;
                g_q [off + cb + j0] = f2tf32(QSCALE*qx);
                g_q [off + cb + j1] = f2tf32(QSCALE*qy);
                g_kt[off + cb + j0] = f2tf32(softplus_f(kx));
                g_kt[off + cb + j1] = f2tf32(softplus_f(ky));
                // transposed V: index = (bb*1024 + h*64 + d)*SSL + token
                int token = r & (SSL-1);
                int bidx  = r >> 11;
                size_t vb = ((size_t)(bidx*1024 + c))*SSL + token;
                g_vt[vb]       = f2tf32(qx+kx);
                g_vt[vb + SSL] = f2tf32(qy+ky);
            }
        }
    }
}

// ---------------------------------------------------------------------------
// Flash attention v9 (r13 + fused exp/PV interleave):
// Q-tile 128, 256 threads (8 warps, warp tile 16x64), 2 CTAs/SM.
// Q/K dim-interleaved -> S-phase LDS.64. V dim-major -> PV LDS.64.
// P stays in registers. Per key-block nt: exp (MUFU) immediately followed
// by that block's 8 PV MMAs -> MUFU of nt+1 overlaps tensor of nt within
// the warp (previously all exps then all PVs = phase bubbles).
// No-max ex2 softmax; masked query rows p = 1 (reference's uniform softmax).
// ---------------------------------------------------------------------------
#define AQ_STR 72
#define AK_STR 72
#define AV_STR 72
#define KBUF (64*AK_STR)
#define VBUF (64*AV_STR)
#define SMEM_ATTN ((128*AQ_STR + 2*KBUF + 2*VBUF)*4)

__global__ void __launch_bounds__(256, 2) attn_tc(
    const int* __restrict__ amask, float* __restrict__ out)
{
    extern __shared__ uint32_t smu[];
    uint32_t* Qs  = smu;                  // [128][AQ_STR] interleaved dims
    uint32_t* KsB = Qs + 128*AQ_STR;      // [2][64][AK_STR] interleaved dims
    uint32_t* VsB = KsB + 2*KBUF;         // [2][64 dims][AV_STR keys]

    const int qt = blockIdx.x, h = blockIdx.y, b = blockIdx.z;
    const int t    = threadIdx.x;
    const int warp = t >> 5;
    const int lane = t & 31;
    const int lq   = lane & 3;
    const int lr   = lane >> 2;
    const int r0 = warp*16 + lr, r1 = r0 + 8;
    const int qrow = t >> 1, qv = t & 1;
    const int krow = t >> 2, kv = t & 3;

    const size_t vtb = ((size_t)(b*1024 + h*HDD + krow))*SSL;

    {   // Q tile + K/V tile 0, all async (verbatim row copies)
        const uint32_t* qg = g_q + ((size_t)(b*SSL + qt*128 + qrow))*DD + h*HDD;
        #pragma unroll
        for (int j = 0; j < 8; j++) {
            int c = 8*qv + j;
            cpa16(&Qs[qrow*AQ_STR + 4*c], qg + 4*c);
        }
        size_t base = ((size_t)(b*SSL + krow))*DD + h*HDD;
        #pragma unroll
        for (int j = 0; j < 4; j++) {
            int c = kv + 4*j;
            cpa16(&KsB[krow*AK_STR + 4*c], g_kt + base + 4*c);
            cpa16(&VsB[krow*AV_STR + 4*c], g_vt + vtb + 4*c);
        }
        CP_COMMIT();
    }
    const bool mA = (amask[b*SSL + qt*128 + r0] == 0);
    const bool mB = (amask[b*SSL + qt*128 + r1] == 0);

    float tl0 = 0.0f, tl1 = 0.0f;
    float accO[8][4] = {};

    for (int it = 0; it < SSL/64; it++) {
        CP_WAIT0();
        __syncthreads();            // current buf fully resident + visible
        const int buf = it & 1;
        uint32_t* Ks = KsB + buf*KBUF;
        uint32_t* Vs = VsB + buf*VBUF;

        if (it + 1 < SSL/64) {      // prefetch next tile into buf^1
            uint32_t* Kn = KsB + (buf^1)*KBUF;
            uint32_t* Vn = VsB + (buf^1)*VBUF;
            size_t base = ((size_t)(b*SSL + (it+1)*64 + krow))*DD + h*HDD;
            size_t vtn  = vtb + (it+1)*64;
            #pragma unroll
            for (int j = 0; j < 4; j++) {
                int c = kv + 4*j;
                cpa16(&Kn[krow*AK_STR + 4*c], g_kt + base + 4*c);
                cpa16(&Vn[krow*AV_STR + 4*c], g_vt + vtn + 4*c);
            }
            CP_COMMIT();
        }

        // ---- S' = (Q*qscale) @ K^T : warp computes 16x64, LDS.64 frags ----
        float accS[8][4] = {};
        #pragma unroll
        for (int ks = 0; ks < 8; ks++) {
            int kb = ks * 8;
            uint32_t a[4];
            uint2 u0 = *(const uint2*)&Qs[r0*AQ_STR + kb + 2*lq];
            uint2 u1 = *(const uint2*)&Qs[r1*AQ_STR + kb + 2*lq];
            a[0] = u0.x; a[1] = u1.x; a[2] = u0.y; a[3] = u1.y;
            #pragma unroll
            for (int nt = 0; nt < 8; nt++) {
                uint2 bb = *(const uint2*)&Ks[(8*nt + lr)*AK_STR + kb + 2*lq];
                mma_tf32(accS[nt], a, bb.x, bb.y);
            }
        }

        // ---- fused softmax + PV per key-block:
        //      exp(nt) on MUFU overlaps PV(nt-1) on tensor ----
        #pragma unroll
        for (int nt = 0; nt < 8; nt++) {          // nt = key 8-block
            float p0 = mA ? 1.0f : ex2f(accS[nt][0]);
            float p1 = mA ? 1.0f : ex2f(accS[nt][1]);
            float p2 = mB ? 1.0f : ex2f(accS[nt][2]);
            float p3 = mB ? 1.0f : ex2f(accS[nt][3]);
            tl0 += p0 + p1;
            tl1 += p2 + p3;
            uint32_t a[4];
            a[0] = __float_as_uint(p0);   // P[r0][key 2lq]   -> slot lq
            a[1] = __float_as_uint(p2);   // P[r1][key 2lq]
            a[2] = __float_as_uint(p1);   // P[r0][key 2lq+1] -> slot lq+4
            a[3] = __float_as_uint(p3);   // P[r1][key 2lq+1]
            #pragma unroll
            for (int d = 0; d < 8; d++) {
                uint2 bb = *(const uint2*)&Vs[(8*d + lr)*AV_STR + 8*nt + 2*lq];
                mma_tf32(accO[d], a, bb.x, bb.y);
            }
        }
    }

    // ---- epilogue: reduce l across quad, write O / l ----
    tl0 += __shfl_xor_sync(0xffffffffu, tl0, 1);
    tl0 += __shfl_xor_sync(0xffffffffu, tl0, 2);
    tl1 += __shfl_xor_sync(0xffffffffu, tl1, 1);
    tl1 += __shfl_xor_sync(0xffffffffu, tl1, 2);
    float li0 = 1.0f / tl0, li1 = 1.0f / tl1;
    size_t row0 = (size_t)(b*SSL + qt*128 + r0) * DD + h*HDD;
    size_t row1 = (size_t)(b*SSL + qt*128 + r1) * DD + h*HDD;
    #pragma unroll
    for (int d = 0; d < 8; d++) {
        int col = 8*d + 2*lq;
        *(float2*)(out + row0 + col) = make_float2(accO[d][0]*li0, accO[d][1]*li0);
        *(float2*)(out + row1 + col) = make_float2(accO[d][2]*li1, accO[d][3]*li1);
    }
}

// ---------------------------------------------------------------------------
extern "C" void kernel_launch(void* const* d_in, const int* in_sizes, int n_in,
                              void* d_out, int out_size)
{
    const float* X     = (const float*)d_in[0];
    const int*   amask = (const int*)  d_in[1];
    const float* Wq    = (const float*)d_in[2];
    const float* bq    = (const float*)d_in[3];
    const float* Wk    = (const float*)d_in[4];
    const float* bk    = (const float*)d_in[5];
    float*       out   = (float*)d_out;

    cudaFuncSetAttribute(proj_tc,
                         cudaFuncAttributeMaxDynamicSharedMemorySize, PROJ_SMEM);
    cudaFuncSetAttribute(attn_tc,
                         cudaFuncAttributeMaxDynamicSharedMemorySize, SMEM_ATTN);

    proj_tc<<<dim3(DD/64, MSZ/128), 256, PROJ_SMEM>>>(X, Wq, bq, Wk, bk);
    attn_tc<<<dim3(SSL/128, HH, BB), 256, SMEM_ATTN>>>(amask, out);
}

// round 16
// speedup vs baseline: 1.0853x; 1.0591x over previous
#include <cuda_runtime.h>
#include <math.h>
#include <stdint.h>

#define BB  2
#define SSL 2048
#define DD  1024
#define HH  16
#define HDD 64
#define MSZ (BB*SSL)

// Scratch (allocation-free rule: device globals). All tf32 bit patterns:
// g_q  = tf32(0.125*log2e * Q), dim-interleaved within 8-groups
//        (dim j -> position 2*(j&3)+(j>>2))
// g_kt = tf32(softplus(K)), dim-interleaved (same scheme)
// g_vt = tf32(Q + K), TRANSPOSED per (b,h): [(b*1024 + col)*SSL + token]
__device__ uint32_t g_q [MSZ*DD];
__device__ uint32_t g_kt[MSZ*DD];
__device__ uint32_t g_vt[MSZ*DD];

// ---------------------------------------------------------------------------
// helpers
// ---------------------------------------------------------------------------
__device__ __forceinline__ uint32_t f2tf32(float x) {
    uint32_t r;
    asm("cvt.rna.tf32.f32 %0, %1;" : "=r"(r) : "f"(x));
    return r;
}

__device__ __forceinline__ float ex2f(float x) {
    float r;
    asm("ex2.approx.f32 %0, %1;" : "=f"(r) : "f"(x));
    return r;
}

__device__ __forceinline__ void mma_tf32(float c[4], const uint32_t a[4],
                                         uint32_t b0, uint32_t b1) {
    asm volatile(
        "mma.sync.aligned.m16n8k8.row.col.f32.tf32.tf32.f32 "
        "{%0,%1,%2,%3}, {%4,%5,%6,%7}, {%8,%9}, {%0,%1,%2,%3};"
        : "+f"(c[0]), "+f"(c[1]), "+f"(c[2]), "+f"(c[3])
        : "r"(a[0]), "r"(a[1]), "r"(a[2]), "r"(a[3]), "r"(b0), "r"(b1));
}

__device__ __forceinline__ float softplus_f(float x) {
    return (x > 15.0f) ? x : log1pf(__expf(x));
}

__device__ __forceinline__ void cpa16(void* s, const void* g) {
    uint32_t sa = (uint32_t)__cvta_generic_to_shared(s);
    asm volatile("cp.async.ca.shared.global [%0], [%1], 16;" :: "r"(sa), "l"(g));
}
#define CP_COMMIT() asm volatile("cp.async.commit_group;")
#define CP_WAIT0()  asm volatile("cp.async.wait_group 0;")

// Q scale: 1/sqrt(HD)=1/8 fused with log2(e) so softmax is a bare ex2.
#define QSCALE (0.125f * 1.44269504f)

// ---------------------------------------------------------------------------
// Fused projection (r6 body, known-good, UNCHANGED): Q and K on the same X
// tile. Epilogue writes tf32 bits: g_q (scaled, interleaved), g_kt (softplus,
// interleaved), g_vt (Q+K, transposed per (b,h)). CTA 128m x 64n, k-tile 32.
// ---------------------------------------------------------------------------
#define XS_STR 36
#define WS_STR 72
#define XS_BUF (128*XS_STR)
#define WS_BUF (32*WS_STR)
#define PROJ_SMEM ((2*XS_BUF + 4*WS_BUF)*4)

__global__ void __launch_bounds__(256, 2) proj_tc(
    const float* __restrict__ X,
    const float* __restrict__ Wq, const float* __restrict__ bq,
    const float* __restrict__ Wk, const float* __restrict__ bk)
{
    extern __shared__ uint32_t psm[];
    uint32_t* XsB  = psm;
    uint32_t* WqsB = psm + 2*XS_BUF;
    uint32_t* WksB = WqsB + 2*WS_BUF;

    const int m0 = blockIdx.y * 128;
    const int n0 = blockIdx.x * 64;
    const int t    = threadIdx.x;
    const int warp = t >> 5;
    const int lane = t & 31;
    const int lq   = lane & 3;
    const int lr   = lane >> 2;
    const int wm = (warp >> 1) * 32;
    const int wn = (warp & 1) * 32;

    const int xr = t >> 1;
    const int xcb = (t & 1) * 4;
    const int wr = t >> 3;
    const int wcb = t & 7;

    float accq[2][4][4] = {};
    float acck[2][4][4] = {};

    {
        const float* xp = X + (size_t)(m0 + xr) * DD;
        #pragma unroll
        for (int j = 0; j < 4; j++) {
            int c = xcb + j;
            float4 f = *(const float4*)(xp + 4*c);
            *(uint4*)&XsB[xr*XS_STR + 4*c] =
                make_uint4(f2tf32(f.x), f2tf32(f.y), f2tf32(f.z), f2tf32(f.w));
        }
        const float* wqp = Wq + (size_t)wr * DD + n0;
        const float* wkp = Wk + (size_t)wr * DD + n0;
        #pragma unroll
        for (int j = 0; j < 2; j++) {
            int c = wcb + 8*j;
            float4 fq = *(const float4*)(wqp + 4*c);
            *(uint4*)&WqsB[wr*WS_STR + 4*c] =
                make_uint4(f2tf32(fq.x), f2tf32(fq.y), f2tf32(fq.z), f2tf32(fq.w));
            float4 fk = *(const float4*)(wkp + 4*c);
            *(uint4*)&WksB[wr*WS_STR + 4*c] =
                make_uint4(f2tf32(fk.x), f2tf32(fk.y), f2tf32(fk.z), f2tf32(fk.w));
        }
    }
    __syncthreads();

    for (int k0 = 0; k0 < DD; k0 += 32) {
        const int buf = (k0 >> 5) & 1;
        uint32_t* Xs  = XsB  + buf*XS_BUF;
        uint32_t* Wqs = WqsB + buf*WS_BUF;
        uint32_t* Wks = WksB + buf*WS_BUF;
        const bool more = (k0 + 32) < DD;

        float4 xst[4], wqst[2], wkst[2];
        if (more) {
            const float* xp = X + (size_t)(m0 + xr) * DD + k0 + 32;
            #pragma unroll
            for (int j = 0; j < 4; j++)
                xst[j] = *(const float4*)(xp + 4*(xcb + j));
            const float* wqp = Wq + (size_t)(k0 + 32 + wr) * DD + n0;
            const float* wkp = Wk + (size_t)(k0 + 32 + wr) * DD + n0;
            #pragma unroll
            for (int j = 0; j < 2; j++) {
                wqst[j] = *(const float4*)(wqp + 4*(wcb + 8*j));
                wkst[j] = *(const float4*)(wkp + 4*(wcb + 8*j));
            }
        }

        #pragma unroll
        for (int ks = 0; ks < 4; ks++) {
            int kb = ks * 8;
            uint32_t a[2][4];
            #pragma unroll
            for (int mt = 0; mt < 2; mt++) {
                int ar = wm + 16*mt + lr;
                a[mt][0] = Xs[ar*XS_STR + kb + lq];
                a[mt][1] = Xs[(ar+8)*XS_STR + kb + lq];
                a[mt][2] = Xs[ar*XS_STR + kb + lq + 4];
                a[mt][3] = Xs[(ar+8)*XS_STR + kb + lq + 4];
            }
            #pragma unroll
            for (int nt = 0; nt < 4; nt++) {
                int bc = wn + 8*nt + lr;
                uint32_t q0 = Wqs[(kb + lq)*WS_STR + bc];
                uint32_t q1 = Wqs[(kb + 4 + lq)*WS_STR + bc];
                uint32_t k0r = Wks[(kb + lq)*WS_STR + bc];
                uint32_t k1r = Wks[(kb + 4 + lq)*WS_STR + bc];
                #pragma unroll
                for (int mt = 0; mt < 2; mt++) {
                    mma_tf32(accq[mt][nt], a[mt], q0, q1);
                    mma_tf32(acck[mt][nt], a[mt], k0r, k1r);
                }
            }
        }

        if (more) {
            uint32_t* Xn  = XsB  + (buf^1)*XS_BUF;
            uint32_t* Wqn = WqsB + (buf^1)*WS_BUF;
            uint32_t* Wkn = WksB + (buf^1)*WS_BUF;
            #pragma unroll
            for (int j = 0; j < 4; j++) {
                float4 f = xst[j];
                *(uint4*)&Xn[xr*XS_STR + 4*(xcb + j)] =
                    make_uint4(f2tf32(f.x), f2tf32(f.y), f2tf32(f.z), f2tf32(f.w));
            }
            #pragma unroll
            for (int j = 0; j < 2; j++) {
                float4 fq = wqst[j];
                *(uint4*)&Wqn[wr*WS_STR + 4*(wcb + 8*j)] =
                    make_uint4(f2tf32(fq.x), f2tf32(fq.y), f2tf32(fq.z), f2tf32(fq.w));
                float4 fk = wkst[j];
                *(uint4*)&Wkn[wr*WS_STR + 4*(wcb + 8*j)] =
                    make_uint4(f2tf32(fk.x), f2tf32(fk.y), f2tf32(fk.z), f2tf32(fk.w));
            }
        }
        __syncthreads();
    }

    // epilogue: g_q/g_kt interleaved tf32 bits; g_vt transposed tf32 bits
    #pragma unroll
    for (int nt = 0; nt < 4; nt++) {
        int c = n0 + wn + 8*nt + 2*lq;
        float bqx = bq[c], bqy = bq[c+1];
        float bkx = bk[c], bky = bk[c+1];
        int cb = c & ~7, j = c & 7;
        int j0 = 2*(j&3) + (j>>2);
        int j1 = 2*((j+1)&3) + ((j+1)>>2);
        #pragma unroll
        for (int mt = 0; mt < 2; mt++) {
            #pragma unroll
            for (int half = 0; half < 2; half++) {
                int r = m0 + wm + 16*mt + lr + 8*half;
                float qx = accq[mt][nt][2*half+0] + bqx;
                float qy = accq[mt][nt][2*half+1] + bqy;
                float kx = acck[mt][nt][2*half+0] + bkx;
                float ky = acck[mt][nt][2*half+1] + bky;
                size_t off = (size_t)r * DD;
                g_q [off + cb + j0] = f2tf32(QSCALE*qx);
                g_q [off + cb + j1] = f2tf32(QSCALE*qy);
                g_kt[off + cb + j0] = f2tf32(softplus_f(kx));
                g_kt[off + cb + j1] = f2tf32(softplus_f(ky));
                // transposed V: index = (bb*1024 + h*64 + d)*SSL + token
                int token = r & (SSL-1);
                int bidx  = r >> 11;
                size_t vb = ((size_t)(bidx*1024 + c))*SSL + token;
                g_vt[vb]       = f2tf32(qx+kx);
                g_vt[vb + SSL] = f2tf32(qy+ky);
            }
        }
    }
}

// ---------------------------------------------------------------------------
// Flash attention v10 (r15 + Q-in-registers + streamed S halves):
// Q-tile 128, 256 threads (8 warps, warp tile 16x64), 2 CTAs/SM.
// Q fragments loaded ONCE from interleaved global into registers (aq[8][4],
// LDG.64) and held across all 32 key tiles -> the Qs smem buffer and its
// per-tile LDS/STS traffic are gone. S computed in two 32-key halves
// (accS[4][4] = 16 regs) each immediately followed by fused exp+PV for
// those key blocks -> S-half-1 MMAs overlap PV-half-0 on the tensor queue.
// K dim-interleaved -> S-phase LDS.64; V dim-major -> PV LDS.64.
// No-max ex2 softmax; masked query rows p = 1 (reference's uniform softmax).
// ---------------------------------------------------------------------------
#define AK_STR 72
#define AV_STR 72
#define KBUF (64*AK_STR)
#define VBUF (64*AV_STR)
#define SMEM_ATTN ((2*KBUF + 2*VBUF)*4)

__global__ void __launch_bounds__(256, 2) attn_tc(
    const int* __restrict__ amask, float* __restrict__ out)
{
    extern __shared__ uint32_t smu[];
    uint32_t* KsB = smu;                  // [2][64][AK_STR] interleaved dims
    uint32_t* VsB = KsB + 2*KBUF;         // [2][64 dims][AV_STR keys]

    const int qt = blockIdx.x, h = blockIdx.y, b = blockIdx.z;
    const int t    = threadIdx.x;
    const int warp = t >> 5;
    const int lane = t & 31;
    const int lq   = lane & 3;
    const int lr   = lane >> 2;
    const int r0 = warp*16 + lr, r1 = r0 + 8;
    const int krow = t >> 2, kv = t & 3;

    const size_t vtb = ((size_t)(b*1024 + h*HDD + krow))*SSL;

    {   // K/V tile 0 async
        size_t base = ((size_t)(b*SSL + krow))*DD + h*HDD;
        #pragma unroll
        for (int j = 0; j < 4; j++) {
            int c = kv + 4*j;
            cpa16(&KsB[krow*AK_STR + 4*c], g_kt + base + 4*c);
            cpa16(&VsB[krow*AV_STR + 4*c], g_vt + vtb + 4*c);
        }
        CP_COMMIT();
    }

    // Q fragments: loaded once, resident in registers for all key tiles.
    // Interleaved layout -> (k=8ks+lq, k=8ks+lq+4) adjacent -> LDG.64.
    uint32_t aq[8][4];
    {
        const uint32_t* q0p = g_q + ((size_t)(b*SSL + qt*128 + r0))*DD + h*HDD;
        const uint32_t* q1p = g_q + ((size_t)(b*SSL + qt*128 + r1))*DD + h*HDD;
        #pragma unroll
        for (int ks = 0; ks < 8; ks++) {
            uint2 u0 = *(const uint2*)(q0p + 8*ks + 2*lq);
            uint2 u1 = *(const uint2*)(q1p + 8*ks + 2*lq);
            aq[ks][0] = u0.x; aq[ks][1] = u1.x;
            aq[ks][2] = u0.y; aq[ks][3] = u1.y;
        }
    }
    const bool mA = (amask[b*SSL + qt*128 + r0] == 0);
    const bool mB = (amask[b*SSL + qt*128 + r1] == 0);

    float tl0 = 0.0f, tl1 = 0.0f;
    float accO[8][4] = {};

    for (int it = 0; it < SSL/64; it++) {
        CP_WAIT0();
        __syncthreads();            // current buf fully resident + visible
        const int buf = it & 1;
        uint32_t* Ks = KsB + buf*KBUF;
        uint32_t* Vs = VsB + buf*VBUF;

        if (it + 1 < SSL/64) {      // prefetch next tile into buf^1
            uint32_t* Kn = KsB + (buf^1)*KBUF;
            uint32_t* Vn = VsB + (buf^1)*VBUF;
            size_t base = ((size_t)(b*SSL + (it+1)*64 + krow))*DD + h*HDD;
            size_t vtn  = vtb + (it+1)*64;
            #pragma unroll
            for (int j = 0; j < 4; j++) {
                int c = kv + 4*j;
                cpa16(&Kn[krow*AK_STR + 4*c], g_kt + base + 4*c);
                cpa16(&Vn[krow*AV_STR + 4*c], g_vt + vtn + 4*c);
            }
            CP_COMMIT();
        }

        // ---- two streamed halves: S(32 keys) then fused exp+PV ----
        #pragma unroll
        for (int half = 0; half < 2; half++) {
            float accS[4][4] = {};
            #pragma unroll
            for (int ks = 0; ks < 8; ks++) {
                int kb = ks * 8;
                #pragma unroll
                for (int j = 0; j < 4; j++) {
                    int nt = 4*half + j;
                    uint2 bb = *(const uint2*)&Ks[(8*nt + lr)*AK_STR + kb + 2*lq];
                    mma_tf32(accS[j], aq[ks], bb.x, bb.y);
                }
            }
            #pragma unroll
            for (int j = 0; j < 4; j++) {
                int nt = 4*half + j;
                float p0 = mA ? 1.0f : ex2f(accS[j][0]);
                float p1 = mA ? 1.0f : ex2f(accS[j][1]);
                float p2 = mB ? 1.0f : ex2f(accS[j][2]);
                float p3 = mB ? 1.0f : ex2f(accS[j][3]);
                tl0 += p0 + p1;
                tl1 += p2 + p3;
                uint32_t a[4];
                a[0] = __float_as_uint(p0);   // P[r0][key 2lq]   -> slot lq
                a[1] = __float_as_uint(p2);   // P[r1][key 2lq]
                a[2] = __float_as_uint(p1);   // P[r0][key 2lq+1] -> slot lq+4
                a[3] = __float_as_uint(p3);   // P[r1][key 2lq+1]
                #pragma unroll
                for (int d = 0; d < 8; d++) {
                    uint2 bb = *(const uint2*)&Vs[(8*d + lr)*AV_STR + 8*nt + 2*lq];
                    mma_tf32(accO[d], a, bb.x, bb.y);
                }
            }
        }
    }

    // ---- epilogue: reduce l across quad, write O / l ----
    tl0 += __shfl_xor_sync(0xffffffffu, tl0, 1);
    tl0 += __shfl_xor_sync(0xffffffffu, tl0, 2);
    tl1 += __shfl_xor_sync(0xffffffffu, tl1, 1);
    tl1 += __shfl_xor_sync(0xffffffffu, tl1, 2);
    float li0 = 1.0f / tl0, li1 = 1.0f / tl1;
    size_t row0 = (size_t)(b*SSL + qt*128 + r0) * DD + h*HDD;
    size_t row1 = (size_t)(b*SSL + qt*128 + r1) * DD + h*HDD;
    #pragma unroll
    for (int d = 0; d < 8; d++) {
        int col = 8*d + 2*lq;
        *(float2*)(out + row0 + col) = make_float2(accO[d][0]*li0, accO[d][1]*li0);
        *(float2*)(out + row1 + col) = make_float2(accO[d][2]*li1, accO[d][3]*li1);
    }
}

// ---------------------------------------------------------------------------
extern "C" void kernel_launch(void* const* d_in, const int* in_sizes, int n_in,
                              void* d_out, int out_size)
{
    const float* X     = (const float*)d_in[0];
    const int*   amask = (const int*)  d_in[1];
    const float* Wq    = (const float*)d_in[2];
    const float* bq    = (const float*)d_in[3];
    const float* Wk    = (const float*)d_in[4];
    const float* bk    = (const float*)d_in[5];
    float*       out   = (float*)d_out;

    cudaFuncSetAttribute(proj_tc,
                         cudaFuncAttributeMaxDynamicSharedMemorySize, PROJ_SMEM);
    cudaFuncSetAttribute(attn_tc,
                         cudaFuncAttributeMaxDynamicSharedMemorySize, SMEM_ATTN);

    proj_tc<<<dim3(DD/64, MSZ/128), 256, PROJ_SMEM>>>(X, Wq, bq, Wk, bk);
    attn_tc<<<dim3(SSL/128, HH, BB), 256, SMEM_ATTN>>>(amask, out);
}

// round 17
// speedup vs baseline: 1.5367x; 1.4159x over previous
#include <cuda_runtime.h>
#include <cuda_fp16.h>
#include <math.h>
#include <stdint.h>

#define BB  2
#define SSL 2048
#define DD  1024
#define HH  16
#define HDD 64
#define MSZ (BB*SSL)

// Device globals (allocation-free rule). fp16 operand images for attn:
// g_qh : fp16(QSCALE*Q),     [token][DD], dim-PAIRS interleaved per 16-group
//        (pair i=(d>>1)&7 -> pos 2*(i&3)+(i>>2); elems keep low/high order)
// g_kth: fp16(softplus(K)),  same layout
// g_vth: fp16(Q+K), transposed per (b,h): [(b*1024+col)][SSL tokens],
//        token-pairs interleaved per 16-group (same scheme on tokens)
__device__ uint32_t g_qh [MSZ*DD/2];
__device__ uint32_t g_kth[MSZ*DD/2];
__device__ uint32_t g_vth[MSZ*DD/2];

// ---------------------------------------------------------------------------
// helpers
// ---------------------------------------------------------------------------
__device__ __forceinline__ uint32_t f2tf32(float x) {
    uint32_t r;
    asm("cvt.rna.tf32.f32 %0, %1;" : "=r"(r) : "f"(x));
    return r;
}
__device__ __forceinline__ float ex2f(float x) {
    float r;
    asm("ex2.approx.f32 %0, %1;" : "=f"(r) : "f"(x));
    return r;
}
__device__ __forceinline__ uint32_t packh2(float lo, float hi) {
    __half2 h = __floats2half2_rn(lo, hi);   // .x = lo (low 16 bits)
    return *(uint32_t*)&h;
}
__device__ __forceinline__ void mma_tf32(float c[4], const uint32_t a[4],
                                         uint32_t b0, uint32_t b1) {
    asm volatile(
        "mma.sync.aligned.m16n8k8.row.col.f32.tf32.tf32.f32 "
        "{%0,%1,%2,%3}, {%4,%5,%6,%7}, {%8,%9}, {%0,%1,%2,%3};"
        : "+f"(c[0]), "+f"(c[1]), "+f"(c[2]), "+f"(c[3])
        : "r"(a[0]), "r"(a[1]), "r"(a[2]), "r"(a[3]), "r"(b0), "r"(b1));
}
__device__ __forceinline__ void mma_f16(float c[4], const uint32_t a[4],
                                        uint32_t b0, uint32_t b1) {
    asm volatile(
        "mma.sync.aligned.m16n8k16.row.col.f32.f16.f16.f32 "
        "{%0,%1,%2,%3}, {%4,%5,%6,%7}, {%8,%9}, {%0,%1,%2,%3};"
        : "+f"(c[0]), "+f"(c[1]), "+f"(c[2]), "+f"(c[3])
        : "r"(a[0]), "r"(a[1]), "r"(a[2]), "r"(a[3]), "r"(b0), "r"(b1));
}
__device__ __forceinline__ float softplus_f(float x) {
    return (x > 15.0f) ? x : log1pf(__expf(x));
}
__device__ __forceinline__ void cpa16(void* s, const void* g) {
    uint32_t sa = (uint32_t)__cvta_generic_to_shared(s);
    asm volatile("cp.async.ca.shared.global [%0], [%1], 16;" :: "r"(sa), "l"(g));
}
#define CP_COMMIT() asm volatile("cp.async.commit_group;")
#define CP_WAIT0()  asm volatile("cp.async.wait_group 0;")

// Q scale: 1/sqrt(HD)=1/8 fused with log2(e) so softmax is a bare ex2.
#define QSCALE (0.125f * 1.44269504f)

// ---------------------------------------------------------------------------
// Fused projection (r6 body, known-good mainloop in tf32). Epilogue now
// emits the fp16 operand images g_qh / g_kth / g_vth described above.
// CTA 128m x 64n, k-tile 32, double-buffered smem.
// ---------------------------------------------------------------------------
#define XS_STR 36
#define WS_STR 72
#define XS_BUF (128*XS_STR)
#define WS_BUF (32*WS_STR)
#define PROJ_SMEM ((2*XS_BUF + 4*WS_BUF)*4)

__global__ void __launch_bounds__(256, 2) proj_tc(
    const float* __restrict__ X,
    const float* __restrict__ Wq, const float* __restrict__ bq,
    const float* __restrict__ Wk, const float* __restrict__ bk)
{
    extern __shared__ uint32_t psm[];
    uint32_t* XsB  = psm;
    uint32_t* WqsB = psm + 2*XS_BUF;
    uint32_t* WksB = WqsB + 2*WS_BUF;

    const int m0 = blockIdx.y * 128;
    const int n0 = blockIdx.x * 64;
    const int t    = threadIdx.x;
    const int warp = t >> 5;
    const int lane = t & 31;
    const int lq   = lane & 3;
    const int lr   = lane >> 2;
    const int wm = (warp >> 1) * 32;
    const int wn = (warp & 1) * 32;

    const int xr = t >> 1;
    const int xcb = (t & 1) * 4;
    const int wr = t >> 3;
    const int wcb = t & 7;

    float accq[2][4][4] = {};
    float acck[2][4][4] = {};

    {
        const float* xp = X + (size_t)(m0 + xr) * DD;
        #pragma unroll
        for (int j = 0; j < 4; j++) {
            int c = xcb + j;
            float4 f = *(const float4*)(xp + 4*c);
            *(uint4*)&XsB[xr*XS_STR + 4*c] =
                make_uint4(f2tf32(f.x), f2tf32(f.y), f2tf32(f.z), f2tf32(f.w));
        }
        const float* wqp = Wq + (size_t)wr * DD + n0;
        const float* wkp = Wk + (size_t)wr * DD + n0;
        #pragma unroll
        for (int j = 0; j < 2; j++) {
            int c = wcb + 8*j;
            float4 fq = *(const float4*)(wqp + 4*c);
            *(uint4*)&WqsB[wr*WS_STR + 4*c] =
                make_uint4(f2tf32(fq.x), f2tf32(fq.y), f2tf32(fq.z), f2tf32(fq.w));
            float4 fk = *(const float4*)(wkp + 4*c);
            *(uint4*)&WksB[wr*WS_STR + 4*c] =
                make_uint4(f2tf32(fk.x), f2tf32(fk.y), f2tf32(fk.z), f2tf32(fk.w));
        }
    }
    __syncthreads();

    for (int k0 = 0; k0 < DD; k0 += 32) {
        const int buf = (k0 >> 5) & 1;
        uint32_t* Xs  = XsB  + buf*XS_BUF;
        uint32_t* Wqs = WqsB + buf*WS_BUF;
        uint32_t* Wks = WksB + buf*WS_BUF;
        const bool more = (k0 + 32) < DD;

        float4 xst[4], wqst[2], wkst[2];
        if (more) {
            const float* xp = X + (size_t)(m0 + xr) * DD + k0 + 32;
            #pragma unroll
            for (int j = 0; j < 4; j++)
                xst[j] = *(const float4*)(xp + 4*(xcb + j));
            const float* wqp = Wq + (size_t)(k0 + 32 + wr) * DD + n0;
            const float* wkp = Wk + (size_t)(k0 + 32 + wr) * DD + n0;
            #pragma unroll
            for (int j = 0; j < 2; j++) {
                wqst[j] = *(const float4*)(wqp + 4*(wcb + 8*j));
                wkst[j] = *(const float4*)(wkp + 4*(wcb + 8*j));
            }
        }

        #pragma unroll
        for (int ks = 0; ks < 4; ks++) {
            int kb = ks * 8;
            uint32_t a[2][4];
            #pragma unroll
            for (int mt = 0; mt < 2; mt++) {
                int ar = wm + 16*mt + lr;
                a[mt][0] = Xs[ar*XS_STR + kb + lq];
                a[mt][1] = Xs[(ar+8)*XS_STR + kb + lq];
                a[mt][2] = Xs[ar*XS_STR + kb + lq + 4];
                a[mt][3] = Xs[(ar+8)*XS_STR + kb + lq + 4];
            }
            #pragma unroll
            for (int nt = 0; nt < 4; nt++) {
                int bc = wn + 8*nt + lr;
                uint32_t q0 = Wqs[(kb + lq)*WS_STR + bc];
                uint32_t q1 = Wqs[(kb + 4 + lq)*WS_STR + bc];
                uint32_t k0r = Wks[(kb + lq)*WS_STR + bc];
                uint32_t k1r = Wks[(kb + 4 + lq)*WS_STR + bc];
                #pragma unroll
                for (int mt = 0; mt < 2; mt++) {
                    mma_tf32(accq[mt][nt], a[mt], q0, q1);
                    mma_tf32(acck[mt][nt], a[mt], k0r, k1r);
                }
            }
        }

        if (more) {
            uint32_t* Xn  = XsB  + (buf^1)*XS_BUF;
            uint32_t* Wqn = WqsB + (buf^1)*WS_BUF;
            uint32_t* Wkn = WksB + (buf^1)*WS_BUF;
            #pragma unroll
            for (int j = 0; j < 4; j++) {
                float4 f = xst[j];
                *(uint4*)&Xn[xr*XS_STR + 4*(xcb + j)] =
                    make_uint4(f2tf32(f.x), f2tf32(f.y), f2tf32(f.z), f2tf32(f.w));
            }
            #pragma unroll
            for (int j = 0; j < 2; j++) {
                float4 fq = wqst[j];
                *(uint4*)&Wqn[wr*WS_STR + 4*(wcb + 8*j)] =
                    make_uint4(f2tf32(fq.x), f2tf32(fq.y), f2tf32(fq.z), f2tf32(fq.w));
                float4 fk = wkst[j];
                *(uint4*)&Wkn[wr*WS_STR + 4*(wcb + 8*j)] =
                    make_uint4(f2tf32(fk.x), f2tf32(fk.y), f2tf32(fk.z), f2tf32(fk.w));
            }
        }
        __syncthreads();
    }

    // epilogue: fp16 operand images
    #pragma unroll
    for (int nt = 0; nt < 4; nt++) {
        int c = n0 + wn + 8*nt + 2*lq;     // even
        float bqx = bq[c], bqy = bq[c+1];
        float bkx = bk[c], bky = bk[c+1];
        // dim-pair interleave position (within head, 16-dim groups)
        int d  = c & 63;
        int pi = (d >> 1) & 7;
        int unit = (c >> 6)*32 + (d >> 4)*8 + 2*(pi & 3) + (pi >> 2);
        #pragma unroll
        for (int mt = 0; mt < 2; mt++) {
            #pragma unroll
            for (int half = 0; half < 2; half++) {
                int r = m0 + wm + 16*mt + lr + 8*half;
                float qx = accq[mt][nt][2*half+0] + bqx;
                float qy = accq[mt][nt][2*half+1] + bqy;
                float kx = acck[mt][nt][2*half+0] + bkx;
                float ky = acck[mt][nt][2*half+1] + bky;
                size_t rowu = (size_t)r * (DD/2);
                g_qh [rowu + unit] = packh2(QSCALE*qx, QSCALE*qy);
                g_kth[rowu + unit] = packh2(softplus_f(kx), softplus_f(ky));
                // transposed V, token-interleaved within 16-groups
                int token = r & (SSL-1);
                int bidx  = r >> 11;
                int ti = (token & 15) >> 1;
                int tpos = (token & ~15) + (2*(ti & 3) + (ti >> 2))*2 + (token & 1);
                __half* vh = (__half*)g_vth;
                size_t vrow = (size_t)(bidx*1024 + c) * SSL;
                vh[vrow + tpos]       = __float2half_rn(qx + kx);
                vh[vrow + SSL + tpos] = __float2half_rn(qy + ky);
            }
        }
    }
}

// ---------------------------------------------------------------------------
// Flash attention v11 (fp16 m16n8k16): Q-tile 128, 256 threads (8 warps,
// warp tile 16x64), 2 CTAs/SM. Q in registers (16 regs), K/V fp16 in smem
// (row stride 160B -> conflict-free 8B fragment loads). Per warp-tile:
// 32 S-MMAs + 32 PV-MMAs (k=16 each) + 64 LDS.64 — half of r16's counts.
// P packs to fp16x2 A-fragments in registers. No-max ex2 softmax; masked
// query rows p = 1 (reference's uniform softmax). cp.async dbuf K/V.
// ---------------------------------------------------------------------------
#define KSTR 40                    // uint32 per row (64 fp16 + pad; stride8=20)
#define KBUF (64*KSTR)
#define VBUF (64*KSTR)
#define SMEM_ATTN ((2*KBUF + 2*VBUF)*4)

__global__ void __launch_bounds__(256, 2) attn_tc(
    const int* __restrict__ amask, float* __restrict__ out)
{
    extern __shared__ uint32_t smu[];
    uint32_t* KsB = smu;                  // [2][64 keys][KSTR]
    uint32_t* VsB = KsB + 2*KBUF;         // [2][64 dims][KSTR]

    const int qt = blockIdx.x, h = blockIdx.y, b = blockIdx.z;
    const int t    = threadIdx.x;
    const int warp = t >> 5;
    const int lane = t & 31;
    const int lq   = lane & 3;
    const int lr   = lane >> 2;
    const int r0 = warp*16 + lr, r1 = r0 + 8;
    const int krow = t >> 2, kv = t & 3;

    // global bases (uint32 units)
    const size_t vrow = ((size_t)(b*1024 + h*HDD + krow)) * (SSL/2);

    {   // K/V tile 0
        size_t kbase = ((size_t)(b*SSL + krow)) * (DD/2) + h*32;
        #pragma unroll
        for (int j = 0; j < 2; j++) {
            int c = kv + 4*j;
            cpa16(&KsB[krow*KSTR + 4*c], g_kth + kbase + 4*c);
            cpa16(&VsB[krow*KSTR + 4*c], g_vth + vrow + 4*c);
        }
        CP_COMMIT();
    }

    // Q fragments resident in registers: aq[kc][0..3] for 4 k16-chunks
    uint32_t aq[4][4];
    {
        const uint32_t* q0p = g_qh + ((size_t)(b*SSL + qt*128 + r0))*(DD/2) + h*32;
        const uint32_t* q1p = g_qh + ((size_t)(b*SSL + qt*128 + r1))*(DD/2) + h*32;
        #pragma unroll
        for (int kc = 0; kc < 4; kc++) {
            uint2 u0 = *(const uint2*)(q0p + kc*8 + 2*lq);
            uint2 u1 = *(const uint2*)(q1p + kc*8 + 2*lq);
            aq[kc][0] = u0.x; aq[kc][1] = u1.x;
            aq[kc][2] = u0.y; aq[kc][3] = u1.y;
        }
    }
    const bool mA = (amask[b*SSL + qt*128 + r0] == 0);
    const bool mB = (amask[b*SSL + qt*128 + r1] == 0);

    float tl0 = 0.0f, tl1 = 0.0f;
    float accO[8][4] = {};

    for (int it = 0; it < SSL/64; it++) {
        CP_WAIT0();
        __syncthreads();            // current buf fully resident + visible
        const int buf = it & 1;
        uint32_t* Ks = KsB + buf*KBUF;
        uint32_t* Vs = VsB + buf*VBUF;

        if (it + 1 < SSL/64) {      // prefetch next tile into buf^1
            uint32_t* Kn = KsB + (buf^1)*KBUF;
            uint32_t* Vn = VsB + (buf^1)*VBUF;
            size_t kbase = ((size_t)(b*SSL + (it+1)*64 + krow))*(DD/2) + h*32;
            size_t vtn   = vrow + (it+1)*32;
            #pragma unroll
            for (int j = 0; j < 2; j++) {
                int c = kv + 4*j;
                cpa16(&Kn[krow*KSTR + 4*c], g_kth + kbase + 4*c);
                cpa16(&Vn[krow*KSTR + 4*c], g_vth + vtn + 4*c);
            }
            CP_COMMIT();
        }

        // ---- two streamed halves of 32 keys each ----
        #pragma unroll
        for (int half = 0; half < 2; half++) {
            // S: 4 dim-chunks(k16) x 4 key-blocks(n8) = 16 MMAs
            float accS[4][4] = {};
            #pragma unroll
            for (int kc = 0; kc < 4; kc++) {
                #pragma unroll
                for (int j = 0; j < 4; j++) {
                    int key = 8*(4*half + j) + lr;
                    uint2 bb = *(const uint2*)&Ks[key*KSTR + kc*8 + 2*lq];
                    mma_f16(accS[j], aq[kc], bb.x, bb.y);
                }
            }
            // fused exp + PV per 16-key chunk (pairs of key-blocks)
            #pragma unroll
            for (int kk = 0; kk < 2; kk++) {
                float pA[4], pB[4];
                #pragma unroll
                for (int e = 0; e < 4; e++) {
                    pA[e] = (e < 2 ? mA : mB) ? 1.0f : ex2f(accS[2*kk][e]);
                    pB[e] = (e < 2 ? mA : mB) ? 1.0f : ex2f(accS[2*kk+1][e]);
                }
                tl0 += pA[0] + pA[1] + pB[0] + pB[1];
                tl1 += pA[2] + pA[3] + pB[2] + pB[3];
                uint32_t a[4];
                a[0] = packh2(pA[0], pA[1]);   // r0, keys lo-block
                a[1] = packh2(pA[2], pA[3]);   // r1, keys lo-block
                a[2] = packh2(pB[0], pB[1]);   // r0, keys hi-block
                a[3] = packh2(pB[2], pB[3]);   // r1, keys hi-block
                int kck = 2*half + kk;         // 16-key chunk index
                #pragma unroll
                for (int d = 0; d < 8; d++) {
                    uint2 bb = *(const uint2*)&Vs[(8*d + lr)*KSTR + kck*8 + 2*lq];
                    mma_f16(accO[d], a, bb.x, bb.y);
                }
            }
        }
    }

    // ---- epilogue: reduce l across quad, write O / l ----
    tl0 += __shfl_xor_sync(0xffffffffu, tl0, 1);
    tl0 += __shfl_xor_sync(0xffffffffu, tl0, 2);
    tl1 += __shfl_xor_sync(0xffffffffu, tl1, 1);
    tl1 += __shfl_xor_sync(0xffffffffu, tl1, 2);
    float li0 = 1.0f / tl0, li1 = 1.0f / tl1;
    size_t row0 = (size_t)(b*SSL + qt*128 + r0) * DD + h*HDD;
    size_t row1 = (size_t)(b*SSL + qt*128 + r1) * DD + h*HDD;
    #pragma unroll
    for (int d = 0; d < 8; d++) {
        int col = 8*d + 2*lq;
        *(float2*)(out + row0 + col) = make_float2(accO[d][0]*li0, accO[d][1]*li0);
        *(float2*)(out + row1 + col) = make_float2(accO[d][2]*li1, accO[d][3]*li1);
    }
}

// ---------------------------------------------------------------------------
extern "C" void kernel_launch(void* const* d_in, const int* in_sizes, int n_in,
                              void* d_out, int out_size)
{
    const float* X     = (const float*)d_in[0];
    const int*   amask = (const int*)  d_in[1];
    const float* Wq    = (const float*)d_in[2];
    const float* bq    = (const float*)d_in[3];
    const float* Wk    = (const float*)d_in[4];
    const float* bk    = (const float*)d_in[5];
    float*       out   = (float*)d_out;

    cudaFuncSetAttribute(proj_tc,
                         cudaFuncAttributeMaxDynamicSharedMemorySize, PROJ_SMEM);
    cudaFuncSetAttribute(attn_tc,
                         cudaFuncAttributeMaxDynamicSharedMemorySize, SMEM_ATTN);

    proj_tc<<<dim3(DD/64, MSZ/128), 256, PROJ_SMEM>>>(X, Wq, bq, Wk, bk);
    attn_tc<<<dim3(SSL/128, HH, BB), 256, SMEM_ATTN>>>(amask, out);
}